// round 12
// baseline (speedup 1.0000x reference)
#include <cuda_runtime.h>
#include <cuda_bf16.h>
#include <cstdint>

#define HID    1024
#define INTERD 2816
#define BB     4
#define NTOK   32768   // B * N = 4 * 8192
#define ODIM   1024

// ---------------- scratch (static device globals; no allocs) ----------------
__device__ float g_h[BB * HID];
__device__ float g_u[BB * INTERD];
__device__ float g_z[BB * HID];
__device__ float g_o[BB * 2 * HID];
__device__ float g_mod[BB * 2 * HID];
__device__ float g_part[1024];
__device__ float g_ws[2];                              // [0]=1/clip(mean|w|), [1]=clip(mean|w|)
__device__ __align__(16) __nv_bfloat16 g_wq[(long)ODIM * HID];   // ternary weights bf16
__device__ __align__(16) __nv_bfloat16 g_q[(long)NTOK * HID];    // quantized activations bf16 (ints)
__device__ float g_arecip[NTOK];                       // amax/127 * mean|w|

__device__ __forceinline__ float silu_f(float v) { return v / (1.f + expf(-v)); }

// ---------------- modulation chain kernels ----------------
// h[b,d] = sum_k silu(c[b,k]) * W[d,k]   (silu fused into A-load)
__global__ void gemm4_silu_kernel(const float* __restrict__ C, const float* __restrict__ W,
                                  float* __restrict__ out, int K, int D) {
    int warp = threadIdx.x >> 5, lane = threadIdx.x & 31;
    int idx = blockIdx.x * 8 + warp;
    if (idx >= 4 * D) return;
    int b = idx / D, d = idx - b * D;
    const float4* a = (const float4*)(C + (long)b * K);
    const float4* w = (const float4*)(W + (long)d * K);
    int K4 = K >> 2;
    float s = 0.f;
#pragma unroll 8
    for (int k = lane; k < K4; k += 32) {
        float4 av = a[k], wv = w[k];
        s += silu_f(av.x) * wv.x + silu_f(av.y) * wv.y
           + silu_f(av.z) * wv.z + silu_f(av.w) * wv.w;
    }
#pragma unroll
    for (int o = 16; o; o >>= 1) s += __shfl_xor_sync(0xffffffffu, s, o);
    if (lane == 0) out[idx] = s;
}

// u[b,j] = silu(h.w_gate[j]) * (h.w_gate[INTER+j])  — both halves in one warp
__global__ void gemm4gate_kernel(const float* __restrict__ A, const float* __restrict__ W,
                                 float* __restrict__ out) {
    int warp = threadIdx.x >> 5, lane = threadIdx.x & 31;
    int idx = blockIdx.x * 8 + warp;
    if (idx >= 4 * INTERD) return;
    int b = idx / INTERD, j = idx - b * INTERD;
    const float4* a  = (const float4*)(A + (long)b * HID);
    const float4* wg = (const float4*)(W + (long)j * HID);
    const float4* wy = (const float4*)(W + (long)(INTERD + j) * HID);
    float sg = 0.f, sy = 0.f;
#pragma unroll 8
    for (int k = lane; k < HID / 4; k += 32) {
        float4 av = a[k];
        float4 g = wg[k], y = wy[k];
        sg += av.x*g.x + av.y*g.y + av.z*g.z + av.w*g.w;
        sy += av.x*y.x + av.y*y.y + av.z*y.z + av.w*y.w;
    }
#pragma unroll
    for (int o = 16; o; o >>= 1) {
        sg += __shfl_xor_sync(0xffffffffu, sg, o);
        sy += __shfl_xor_sync(0xffffffffu, sy, o);
    }
    if (lane == 0) out[idx] = silu_f(sg) * sy;
}

// out[b,d] = sum_k A[b,k]*W[d,k] (+bias[d]); one warp per output element, float4 loads
__global__ void gemm4_kernel(const float* __restrict__ A, const float* __restrict__ W,
                             const float* __restrict__ bias, float* __restrict__ out,
                             int K, int D) {
    int warp = threadIdx.x >> 5, lane = threadIdx.x & 31;
    int idx = blockIdx.x * 8 + warp;
    if (idx >= 4 * D) return;
    int b = idx / D, d = idx - b * D;
    const float4* a = (const float4*)(A + (long)b * K);
    const float4* w = (const float4*)(W + (long)d * K);
    int K4 = K >> 2;
    float s = 0.f;
#pragma unroll 8
    for (int k = lane; k < K4; k += 32) {
        float4 av = a[k], wv = w[k];
        s += av.x * wv.x + av.y * wv.y + av.z * wv.z + av.w * wv.w;
    }
#pragma unroll
    for (int o = 16; o; o >>= 1) s += __shfl_xor_sync(0xffffffffu, s, o);
    if (lane == 0) out[idx] = s + (bias ? bias[d] : 0.f);
}

__global__ void rms4_kernel(const float* __restrict__ w_norm) {
    __shared__ float sm[256];
    int b = blockIdx.x, tid = threadIdx.x;
    float* o = g_o + b * 2048;
    float s = 0.f;
    for (int i = tid; i < 2048; i += 256) { float v = o[i]; s += v * v; }
    sm[tid] = s; __syncthreads();
    for (int st = 128; st > 0; st >>= 1) { if (tid < st) sm[tid] += sm[tid + st]; __syncthreads(); }
    float rstd = rsqrtf(sm[0] * (1.f / 2048.f) + 1e-6f);
    for (int i = tid; i < 2048; i += 256) o[i] = o[i] * rstd * w_norm[i];
}

// ---------------- weight quant (deterministic reduction) ----------------
__global__ void wabs_partial_kernel(const float* __restrict__ w) {
    __shared__ float sm[256];
    int b = blockIdx.x, tid = threadIdx.x;
    const float* p = w + (long)b * 1024;
    float s = 0.f;
    for (int i = tid; i < 1024; i += 256) s += fabsf(p[i]);
    sm[tid] = s; __syncthreads();
    for (int st = 128; st > 0; st >>= 1) { if (tid < st) sm[tid] += sm[tid + st]; __syncthreads(); }
    if (tid == 0) g_part[b] = sm[0];
}

__global__ void wabs_final_kernel() {
    __shared__ float sm[256];
    int tid = threadIdx.x;
    float s = g_part[tid] + g_part[tid + 256] + g_part[tid + 512] + g_part[tid + 768];
    sm[tid] = s; __syncthreads();
    for (int st = 128; st > 0; st >>= 1) { if (tid < st) sm[tid] += sm[tid + st]; __syncthreads(); }
    if (tid == 0) {
        float mean = sm[0] * (1.f / (1024.f * 1024.f));
        float m = fmaxf(mean, 1e-5f);
        g_ws[0] = 1.f / m;
        g_ws[1] = m;
    }
}

__global__ void wquant_kernel(const float* __restrict__ w) {
    int i = blockIdx.x * 256 + threadIdx.x;           // groups of 4
    if (i < ODIM * HID / 4) {
        float s = g_ws[0];
        const float4 v = ((const float4*)w)[i];
        __nv_bfloat162 lo, hi;
        lo.x = __float2bfloat16(fminf(fmaxf(rintf(v.x * s), -1.f), 1.f));
        lo.y = __float2bfloat16(fminf(fmaxf(rintf(v.y * s), -1.f), 1.f));
        hi.x = __float2bfloat16(fminf(fmaxf(rintf(v.z * s), -1.f), 1.f));
        hi.y = __float2bfloat16(fminf(fmaxf(rintf(v.w * s), -1.f), 1.f));
        ((__nv_bfloat162*)g_wq)[i * 2]     = lo;
        ((__nv_bfloat162*)g_wq)[i * 2 + 1] = hi;
    }
}

// ---------------- activation pipeline: LN -> modulate -> RMSNorm -> quant ----------------
__global__ void aq_kernel(const float* __restrict__ x, const float* __restrict__ wbn) {
    __shared__ float p1[8], p2[8];
    int t = blockIdx.x, tid = threadIdx.x;
    int wid = tid >> 5, lane = tid & 31;
    int b = t >> 13;
    const float4* xr = (const float4*)(x + (long)t * HID);
    const float* mod = g_mod + b * 2048;              // [0:1024) shift, [1024:2048) scale
    float4 v = xr[tid];

    float s = v.x + v.y + v.z + v.w;
    float s2 = v.x*v.x + v.y*v.y + v.z*v.z + v.w*v.w;
#pragma unroll
    for (int o = 16; o; o >>= 1) {
        s  += __shfl_xor_sync(0xffffffffu, s, o);
        s2 += __shfl_xor_sync(0xffffffffu, s2, o);
    }
    if (lane == 0) { p1[wid] = s; p2[wid] = s2; }
    __syncthreads();
    float S = 0.f, S2 = 0.f;
#pragma unroll
    for (int i = 0; i < 8; i++) { S += p1[i]; S2 += p2[i]; }
    float mean = S * (1.f / HID);
    float var = S2 * (1.f / HID) - mean * mean;
    float rstd = rsqrtf(var + 1e-6f);
    __syncthreads();

    int h0 = tid * 4;
    v.x = (v.x - mean) * rstd * (1.f + mod[1024+h0])   + mod[h0];
    v.y = (v.y - mean) * rstd * (1.f + mod[1024+h0+1]) + mod[h0+1];
    v.z = (v.z - mean) * rstd * (1.f + mod[1024+h0+2]) + mod[h0+2];
    v.w = (v.w - mean) * rstd * (1.f + mod[1024+h0+3]) + mod[h0+3];
    float ms = v.x*v.x + v.y*v.y + v.z*v.z + v.w*v.w;
#pragma unroll
    for (int o = 16; o; o >>= 1) ms += __shfl_xor_sync(0xffffffffu, ms, o);
    if (lane == 0) p1[wid] = ms;
    __syncthreads();
    float MS = 0.f;
#pragma unroll
    for (int i = 0; i < 8; i++) MS += p1[i];
    float rr = rsqrtf(MS * (1.f / HID) + 1e-8f);
    __syncthreads();

    v.x *= rr * wbn[h0];   v.y *= rr * wbn[h0+1];
    v.z *= rr * wbn[h0+2]; v.w *= rr * wbn[h0+3];
    float amax = fmaxf(fmaxf(fabsf(v.x), fabsf(v.y)), fmaxf(fabsf(v.z), fabsf(v.w)));
#pragma unroll
    for (int o = 16; o; o >>= 1) amax = fmaxf(amax, __shfl_xor_sync(0xffffffffu, amax, o));
    if (lane == 0) p1[wid] = amax;
    __syncthreads();
    float AM = 0.f;
#pragma unroll
    for (int i = 0; i < 8; i++) AM = fmaxf(AM, p1[i]);
    float am = fmaxf(AM, 1e-5f);
    float sa = 127.f / am;

    __nv_bfloat162 q0, q1;
    q0.x = __float2bfloat16(fminf(fmaxf(rintf(v.x * sa), -128.f), 127.f));
    q0.y = __float2bfloat16(fminf(fmaxf(rintf(v.y * sa), -128.f), 127.f));
    q1.x = __float2bfloat16(fminf(fmaxf(rintf(v.z * sa), -128.f), 127.f));
    q1.y = __float2bfloat16(fminf(fmaxf(rintf(v.w * sa), -128.f), 127.f));
    __nv_bfloat162* qp = (__nv_bfloat162*)(g_q + (long)t * HID);
    qp[tid * 2]     = q0;
    qp[tid * 2 + 1] = q1;
    if (tid == 0) g_arecip[t] = am * (1.f / 127.f) * g_ws[1];
}

// ---------------- main GEMM: 128x256 tile, 512 threads, bf16 mma.sync + ldmatrix ----------------
__device__ __forceinline__ void cp16s(uint32_t saddr, const void* g) {
    asm volatile("cp.async.cg.shared.global [%0], [%1], 16;\n" :: "r"(saddr), "l"(g));
}

#define NSTG      3
#define A_BYTES   16384             // 128 rows x 128 B
#define B_BYTES   32768             // 256 rows x 128 B
#define STG_BYTES 49152             // A + B per stage
#define TCTH      512
#define SW(o) ((o) ^ (((o) >> 3) & 0x70))

extern __shared__ __align__(16) char smdyn[];

__global__ void __launch_bounds__(TCTH, 1) bitgemm_kernel(const float* __restrict__ bias,
                                                          float* __restrict__ out) {
    const int tid = threadIdx.x;
    const int lane = tid & 31, warp = tid >> 5;
    const int wm = warp >> 2, wn = warp & 3;      // 4x4 warp grid: 32 rows x 64 cols per warp
    const long arow0 = (long)blockIdx.y * 128;
    const int brow0 = blockIdx.x * 256;
    const int g = lane >> 2, tg = lane & 3;

    uint32_t sbase;
    asm("{ .reg .u64 t; cvta.to.shared.u64 t, %1; cvt.u32.u64 %0, t; }"
        : "=r"(sbase) : "l"(smdyn));

    // per-lane ldmatrix address deltas
    const int lr = lane & 7, blk = lane >> 3;
    const int rA = lr + (blk & 1) * 8, cA = (blk >> 1) * 8;    // A: blocks 0/1 rows, 2/3 +8 cols
    const int rB = lr + (blk >> 1) * 8, cB = (blk & 1) * 8;    // B: blocks 0/2 n-rows, 1/3 +8 cols

    float acc[2][8][4];
#pragma unroll
    for (int i = 0; i < 2; i++)
#pragma unroll
        for (int j = 0; j < 8; j++)
#pragma unroll
            for (int r = 0; r < 4; r++) acc[i][j][r] = 0.f;

    // loader: chunk kt (64 bf16 wide) -> stage kt%3
    auto load_chunk = [&](int kt) {
        const uint32_t ab = sbase + (kt % NSTG) * STG_BYTES;
        const uint32_t bb = ab + A_BYTES;
        const int k0 = kt * 64;
#pragma unroll
        for (int it = 0; it < 2; it++) {              // A: 1024 16B vecs
            int idx = it * TCTH + tid;
            int row = idx >> 3, u = idx & 7;
            uint32_t off = row * 128 + u * 16;
            cp16s(ab + SW(off), g_q + (arow0 + row) * HID + k0 + u * 8);
        }
#pragma unroll
        for (int it = 0; it < 4; it++) {              // B: 2048 16B vecs (256 rows)
            int idx = it * TCTH + tid;
            int row = idx >> 3, u = idx & 7;
            uint32_t off = row * 128 + u * 16;
            cp16s(bb + SW(off), g_wq + (long)(brow0 + row) * HID + k0 + u * 8);
        }
        asm volatile("cp.async.commit_group;\n");
    };

    load_chunk(0);
    load_chunk(1);

#pragma unroll 1
    for (int kt = 0; kt < 16; kt++) {
        if (kt < 15) asm volatile("cp.async.wait_group 1;\n");
        else         asm volatile("cp.async.wait_group 0;\n");
        __syncthreads();   // orders last iteration's LDSM reads before the overwrite below

        if (kt + 2 < 16) load_chunk(kt + 2);

        const uint32_t ab = sbase + (kt % NSTG) * STG_BYTES;
        const uint32_t bb = ab + A_BYTES;
#pragma unroll
        for (int ks = 0; ks < 4; ks++) {
            const int kb = ks * 16;
            unsigned av[2][4];
#pragma unroll
            for (int i = 0; i < 2; i++) {
                uint32_t off = (uint32_t)(wm * 32 + i * 16 + rA) * 128 + (kb + cA) * 2;
                asm volatile("ldmatrix.sync.aligned.m8n8.x4.shared.b16 {%0,%1,%2,%3}, [%4];"
                             : "=r"(av[i][0]), "=r"(av[i][1]), "=r"(av[i][2]), "=r"(av[i][3])
                             : "r"(ab + SW(off)));
            }
#pragma unroll
            for (int jj = 0; jj < 4; jj++) {
                unsigned bv[4];
                uint32_t off = (uint32_t)(wn * 64 + jj * 16 + rB) * 128 + (kb + cB) * 2;
                asm volatile("ldmatrix.sync.aligned.m8n8.x4.shared.b16 {%0,%1,%2,%3}, [%4];"
                             : "=r"(bv[0]), "=r"(bv[1]), "=r"(bv[2]), "=r"(bv[3])
                             : "r"(bb + SW(off)));
#pragma unroll
                for (int jh = 0; jh < 2; jh++) {
                    int j = jj * 2 + jh;
#pragma unroll
                    for (int i = 0; i < 2; i++) {
                        asm volatile(
                            "mma.sync.aligned.m16n8k16.row.col.f32.bf16.bf16.f32 "
                            "{%0,%1,%2,%3}, {%4,%5,%6,%7}, {%8,%9}, {%0,%1,%2,%3};"
                            : "+f"(acc[i][j][0]), "+f"(acc[i][j][1]),
                              "+f"(acc[i][j][2]), "+f"(acc[i][j][3])
                            : "r"(av[i][0]), "r"(av[i][1]), "r"(av[i][2]), "r"(av[i][3]),
                              "r"(bv[jh * 2]), "r"(bv[jh * 2 + 1]));
                    }
                }
            }
        }
    }

    // epilogue: dequant per token + bias (float2 stores)
#pragma unroll
    for (int i = 0; i < 2; i++) {
        long row = arow0 + wm * 32 + i * 16 + g;
        float r0 = g_arecip[row];
        float r1 = g_arecip[row + 8];
#pragma unroll
        for (int j = 0; j < 8; j++) {
            int col = brow0 + wn * 64 + j * 8 + 2 * tg;
            float b0v = bias[col], b1v = bias[col + 1];
            float2 lo = make_float2(acc[i][j][0] * r0 + b0v, acc[i][j][1] * r0 + b1v);
            float2 hi = make_float2(acc[i][j][2] * r1 + b0v, acc[i][j][3] * r1 + b1v);
            *(float2*)(out + row * ODIM + col)       = lo;
            *(float2*)(out + (row + 8) * ODIM + col) = hi;
        }
    }
}

// ---------------- launch ----------------
extern "C" void kernel_launch(void* const* d_in, const int* in_sizes, int n_in,
                              void* d_out, int out_size) {
    const float* x        = (const float*)d_in[0];
    const float* c        = (const float*)d_in[1];
    const float* w_input  = (const float*)d_in[2];
    const float* w_gate   = (const float*)d_in[3];
    const float* w_down   = (const float*)d_in[4];
    const float* w_output = (const float*)d_in[5];
    const float* b_output = (const float*)d_in[6];
    const float* w_norm   = (const float*)d_in[7];
    const float* w_outp   = (const float*)d_in[8];
    const float* b_outp   = (const float*)d_in[9];
    const float* w_bit    = (const float*)d_in[10];
    const float* b_bit    = (const float*)d_in[11];
    const float* w_bn     = (const float*)d_in[12];
    float* out = (float*)d_out;

    float *p_h, *p_u, *p_z, *p_o, *p_mod;
    cudaGetSymbolAddress((void**)&p_h,   g_h);
    cudaGetSymbolAddress((void**)&p_u,   g_u);
    cudaGetSymbolAddress((void**)&p_z,   g_z);
    cudaGetSymbolAddress((void**)&p_o,   g_o);
    cudaGetSymbolAddress((void**)&p_mod, g_mod);

    // weight quant path (independent)
    wabs_partial_kernel<<<1024, 256>>>(w_bit);
    wabs_final_kernel<<<1, 256>>>();
    wquant_kernel<<<(ODIM * HID / 4) / 256, 256>>>(w_bit);

    // modulation chain (B=4) — silu fused into input proj; gate pair fused
    gemm4_silu_kernel<<<512, 256>>>(c, w_input, p_h, HID, HID);
    gemm4gate_kernel<<<1408, 256>>>(p_h, w_gate, p_u);
    gemm4_kernel<<<512, 256>>>(p_u, w_down, nullptr, p_z, INTERD, HID);
    gemm4_kernel<<<1024, 256>>>(p_z, w_output, b_output, p_o, HID, 2 * HID);
    rms4_kernel<<<4, 256>>>(w_norm);
    gemm4_kernel<<<1024, 256>>>(p_o, w_outp, b_outp, p_mod, 2 * HID, 2 * HID);

    // per-token normalize + bf16-int quantize (shuffle reductions)
    aq_kernel<<<NTOK, 256>>>(x, w_bn);

    // main GEMM: 128x256 tiles, 512 threads, 3-stage (144KB dynamic smem)
    static const int smem_bytes = NSTG * STG_BYTES;   // 147456
    cudaFuncSetAttribute(bitgemm_kernel, cudaFuncAttributeMaxDynamicSharedMemorySize, smem_bytes);
    dim3 ggrid(4, 256);   // n-tiles fastest: 4 column tiles share the A m-tile via L2
    bitgemm_kernel<<<ggrid, TCTH, smem_bytes>>>(b_bit, out);
}

// round 13
// speedup vs baseline: 1.0323x; 1.0323x over previous
#include <cuda_runtime.h>
#include <cuda_bf16.h>
#include <cstdint>

#define HID    1024
#define INTERD 2816
#define BB     4
#define NTOK   32768   // B * N = 4 * 8192
#define ODIM   1024

// ---------------- scratch (static device globals; no allocs) ----------------
__device__ float g_h[BB * HID];
__device__ float g_u[BB * INTERD];
__device__ float g_z[BB * HID];
__device__ float g_o[BB * 2 * HID];
__device__ float g_mod[BB * 2 * HID];
__device__ float g_part[1024];
__device__ float g_ws[2];                              // [0]=1/clip(mean|w|), [1]=clip(mean|w|)
__device__ __align__(16) __nv_bfloat16 g_wq[(long)ODIM * HID];   // ternary weights bf16
__device__ __align__(16) __nv_bfloat16 g_q[(long)NTOK * HID];    // quantized activations bf16 (ints)
__device__ float g_arecip[NTOK];                       // amax/127 * mean|w|

__device__ __forceinline__ float silu_f(float v) { return v / (1.f + expf(-v)); }

// ---------------- modulation chain kernels ----------------
// h[b,d] = sum_k silu(c[b,k]) * W[d,k]   (silu fused into A-load)
__global__ void gemm4_silu_kernel(const float* __restrict__ C, const float* __restrict__ W,
                                  float* __restrict__ out, int K, int D) {
    int warp = threadIdx.x >> 5, lane = threadIdx.x & 31;
    int idx = blockIdx.x * 8 + warp;
    if (idx >= 4 * D) return;
    int b = idx / D, d = idx - b * D;
    const float4* a = (const float4*)(C + (long)b * K);
    const float4* w = (const float4*)(W + (long)d * K);
    int K4 = K >> 2;
    float s = 0.f;
#pragma unroll 8
    for (int k = lane; k < K4; k += 32) {
        float4 av = a[k], wv = w[k];
        s += silu_f(av.x) * wv.x + silu_f(av.y) * wv.y
           + silu_f(av.z) * wv.z + silu_f(av.w) * wv.w;
    }
#pragma unroll
    for (int o = 16; o; o >>= 1) s += __shfl_xor_sync(0xffffffffu, s, o);
    if (lane == 0) out[idx] = s;
}

// u[b,j] = silu(h.w_gate[j]) * (h.w_gate[INTER+j])  — both halves in one warp
__global__ void gemm4gate_kernel(const float* __restrict__ A, const float* __restrict__ W,
                                 float* __restrict__ out) {
    int warp = threadIdx.x >> 5, lane = threadIdx.x & 31;
    int idx = blockIdx.x * 8 + warp;
    if (idx >= 4 * INTERD) return;
    int b = idx / INTERD, j = idx - b * INTERD;
    const float4* a  = (const float4*)(A + (long)b * HID);
    const float4* wg = (const float4*)(W + (long)j * HID);
    const float4* wy = (const float4*)(W + (long)(INTERD + j) * HID);
    float sg = 0.f, sy = 0.f;
#pragma unroll 8
    for (int k = lane; k < HID / 4; k += 32) {
        float4 av = a[k];
        float4 g = wg[k], y = wy[k];
        sg += av.x*g.x + av.y*g.y + av.z*g.z + av.w*g.w;
        sy += av.x*y.x + av.y*y.y + av.z*y.z + av.w*y.w;
    }
#pragma unroll
    for (int o = 16; o; o >>= 1) {
        sg += __shfl_xor_sync(0xffffffffu, sg, o);
        sy += __shfl_xor_sync(0xffffffffu, sy, o);
    }
    if (lane == 0) out[idx] = silu_f(sg) * sy;
}

// out[b,d] = sum_k A[b,k]*W[d,k] (+bias[d]); one warp per output element, float4 loads
__global__ void gemm4_kernel(const float* __restrict__ A, const float* __restrict__ W,
                             const float* __restrict__ bias, float* __restrict__ out,
                             int K, int D) {
    int warp = threadIdx.x >> 5, lane = threadIdx.x & 31;
    int idx = blockIdx.x * 8 + warp;
    if (idx >= 4 * D) return;
    int b = idx / D, d = idx - b * D;
    const float4* a = (const float4*)(A + (long)b * K);
    const float4* w = (const float4*)(W + (long)d * K);
    int K4 = K >> 2;
    float s = 0.f;
#pragma unroll 8
    for (int k = lane; k < K4; k += 32) {
        float4 av = a[k], wv = w[k];
        s += av.x * wv.x + av.y * wv.y + av.z * wv.z + av.w * wv.w;
    }
#pragma unroll
    for (int o = 16; o; o >>= 1) s += __shfl_xor_sync(0xffffffffu, s, o);
    if (lane == 0) out[idx] = s + (bias ? bias[d] : 0.f);
}

__global__ void rms4_kernel(const float* __restrict__ w_norm) {
    __shared__ float sm[256];
    int b = blockIdx.x, tid = threadIdx.x;
    float* o = g_o + b * 2048;
    float s = 0.f;
    for (int i = tid; i < 2048; i += 256) { float v = o[i]; s += v * v; }
    sm[tid] = s; __syncthreads();
    for (int st = 128; st > 0; st >>= 1) { if (tid < st) sm[tid] += sm[tid + st]; __syncthreads(); }
    float rstd = rsqrtf(sm[0] * (1.f / 2048.f) + 1e-6f);
    for (int i = tid; i < 2048; i += 256) o[i] = o[i] * rstd * w_norm[i];
}

// ---------------- weight quant (deterministic reduction) ----------------
__global__ void wabs_partial_kernel(const float* __restrict__ w) {
    __shared__ float sm[256];
    int b = blockIdx.x, tid = threadIdx.x;
    const float* p = w + (long)b * 1024;
    float s = 0.f;
    for (int i = tid; i < 1024; i += 256) s += fabsf(p[i]);
    sm[tid] = s; __syncthreads();
    for (int st = 128; st > 0; st >>= 1) { if (tid < st) sm[tid] += sm[tid + st]; __syncthreads(); }
    if (tid == 0) g_part[b] = sm[0];
}

__global__ void wabs_final_kernel() {
    __shared__ float sm[256];
    int tid = threadIdx.x;
    float s = g_part[tid] + g_part[tid + 256] + g_part[tid + 512] + g_part[tid + 768];
    sm[tid] = s; __syncthreads();
    for (int st = 128; st > 0; st >>= 1) { if (tid < st) sm[tid] += sm[tid + st]; __syncthreads(); }
    if (tid == 0) {
        float mean = sm[0] * (1.f / (1024.f * 1024.f));
        float m = fmaxf(mean, 1e-5f);
        g_ws[0] = 1.f / m;
        g_ws[1] = m;
    }
}

__global__ void wquant_kernel(const float* __restrict__ w) {
    int i = blockIdx.x * 256 + threadIdx.x;           // groups of 4
    if (i < ODIM * HID / 4) {
        float s = g_ws[0];
        const float4 v = ((const float4*)w)[i];
        __nv_bfloat162 lo, hi;
        lo.x = __float2bfloat16(fminf(fmaxf(rintf(v.x * s), -1.f), 1.f));
        lo.y = __float2bfloat16(fminf(fmaxf(rintf(v.y * s), -1.f), 1.f));
        hi.x = __float2bfloat16(fminf(fmaxf(rintf(v.z * s), -1.f), 1.f));
        hi.y = __float2bfloat16(fminf(fmaxf(rintf(v.w * s), -1.f), 1.f));
        ((__nv_bfloat162*)g_wq)[i * 2]     = lo;
        ((__nv_bfloat162*)g_wq)[i * 2 + 1] = hi;
    }
}

// ---------------- activation pipeline: LN -> modulate -> RMSNorm -> quant ----------------
__global__ void aq_kernel(const float* __restrict__ x, const float* __restrict__ wbn) {
    __shared__ float p1[8], p2[8];
    int t = blockIdx.x, tid = threadIdx.x;
    int wid = tid >> 5, lane = tid & 31;
    int b = t >> 13;
    const float4* xr = (const float4*)(x + (long)t * HID);
    const float* mod = g_mod + b * 2048;              // [0:1024) shift, [1024:2048) scale
    float4 v = xr[tid];

    float s = v.x + v.y + v.z + v.w;
    float s2 = v.x*v.x + v.y*v.y + v.z*v.z + v.w*v.w;
#pragma unroll
    for (int o = 16; o; o >>= 1) {
        s  += __shfl_xor_sync(0xffffffffu, s, o);
        s2 += __shfl_xor_sync(0xffffffffu, s2, o);
    }
    if (lane == 0) { p1[wid] = s; p2[wid] = s2; }
    __syncthreads();
    float S = 0.f, S2 = 0.f;
#pragma unroll
    for (int i = 0; i < 8; i++) { S += p1[i]; S2 += p2[i]; }
    float mean = S * (1.f / HID);
    float var = S2 * (1.f / HID) - mean * mean;
    float rstd = rsqrtf(var + 1e-6f);
    __syncthreads();

    int h0 = tid * 4;
    v.x = (v.x - mean) * rstd * (1.f + mod[1024+h0])   + mod[h0];
    v.y = (v.y - mean) * rstd * (1.f + mod[1024+h0+1]) + mod[h0+1];
    v.z = (v.z - mean) * rstd * (1.f + mod[1024+h0+2]) + mod[h0+2];
    v.w = (v.w - mean) * rstd * (1.f + mod[1024+h0+3]) + mod[h0+3];
    float ms = v.x*v.x + v.y*v.y + v.z*v.z + v.w*v.w;
#pragma unroll
    for (int o = 16; o; o >>= 1) ms += __shfl_xor_sync(0xffffffffu, ms, o);
    if (lane == 0) p1[wid] = ms;
    __syncthreads();
    float MS = 0.f;
#pragma unroll
    for (int i = 0; i < 8; i++) MS += p1[i];
    float rr = rsqrtf(MS * (1.f / HID) + 1e-8f);
    __syncthreads();

    v.x *= rr * wbn[h0];   v.y *= rr * wbn[h0+1];
    v.z *= rr * wbn[h0+2]; v.w *= rr * wbn[h0+3];
    float amax = fmaxf(fmaxf(fabsf(v.x), fabsf(v.y)), fmaxf(fabsf(v.z), fabsf(v.w)));
#pragma unroll
    for (int o = 16; o; o >>= 1) amax = fmaxf(amax, __shfl_xor_sync(0xffffffffu, amax, o));
    if (lane == 0) p1[wid] = amax;
    __syncthreads();
    float AM = 0.f;
#pragma unroll
    for (int i = 0; i < 8; i++) AM = fmaxf(AM, p1[i]);
    float am = fmaxf(AM, 1e-5f);
    float sa = 127.f / am;

    __nv_bfloat162 q0, q1;
    q0.x = __float2bfloat16(fminf(fmaxf(rintf(v.x * sa), -128.f), 127.f));
    q0.y = __float2bfloat16(fminf(fmaxf(rintf(v.y * sa), -128.f), 127.f));
    q1.x = __float2bfloat16(fminf(fmaxf(rintf(v.z * sa), -128.f), 127.f));
    q1.y = __float2bfloat16(fminf(fmaxf(rintf(v.w * sa), -128.f), 127.f));
    __nv_bfloat162* qp = (__nv_bfloat162*)(g_q + (long)t * HID);
    qp[tid * 2]     = q0;
    qp[tid * 2 + 1] = q1;
    if (tid == 0) g_arecip[t] = am * (1.f / 127.f) * g_ws[1];
}

// ---------------- main GEMM: R11 config — 128x128 tile, 256 threads, 2 CTA/SM ----------------
__device__ __forceinline__ void cp16s(uint32_t saddr, const void* g) {
    asm volatile("cp.async.cg.shared.global [%0], [%1], 16;\n" :: "r"(saddr), "l"(g));
}

#define NSTG       3
#define OPER_BYTES 16384            // 128 rows x 128 B (one operand, one stage)
#define STG_BYTES  32768            // A + B per stage
#define SW(o) ((o) ^ (((o) >> 3) & 0x70))

extern __shared__ __align__(16) char smdyn[];

__global__ void __launch_bounds__(256, 2) bitgemm_kernel(const float* __restrict__ bias,
                                                         float* __restrict__ out) {
    const int tid = threadIdx.x;
    const int lane = tid & 31, warp = tid >> 5;
    const int wm = warp >> 1, wn = warp & 1;      // 4x2 warp grid: 32 rows x 64 cols per warp
    const long arow0 = (long)blockIdx.y * 128;
    const int brow0 = blockIdx.x * 128;
    const int g = lane >> 2, tg = lane & 3;

    uint32_t sbase;
    asm("{ .reg .u64 t; cvta.to.shared.u64 t, %1; cvt.u32.u64 %0, t; }"
        : "=r"(sbase) : "l"(smdyn));

    // per-lane ldmatrix address deltas
    const int lr = lane & 7, blk = lane >> 3;
    const int rA = lr + (blk & 1) * 8, cA = (blk >> 1) * 8;    // A: blocks 0/1 rows, 2/3 +8 cols
    const int rB = lr + (blk >> 1) * 8, cB = (blk & 1) * 8;    // B: blocks 0/2 n-rows, 1/3 +8 cols

    float acc[2][8][4];
#pragma unroll
    for (int i = 0; i < 2; i++)
#pragma unroll
        for (int j = 0; j < 8; j++)
#pragma unroll
            for (int r = 0; r < 4; r++) acc[i][j][r] = 0.f;

    // loader: chunk kt (64 bf16 wide) -> stage kt%3, SW128-swizzled 128B rows
    auto load_chunk = [&](int kt) {
        const uint32_t ab = sbase + (kt % NSTG) * STG_BYTES;
        const uint32_t bb = ab + OPER_BYTES;
        const int k0 = kt * 64;
#pragma unroll
        for (int it = 0; it < 4; it++) {
            int idx = it * 256 + tid;                 // [0,1024)
            int row = idx >> 3, u = idx & 7;
            uint32_t off = row * 128 + u * 16;
            cp16s(ab + SW(off), g_q + (arow0 + row) * HID + k0 + u * 8);
            cp16s(bb + SW(off), g_wq + (long)(brow0 + row) * HID + k0 + u * 8);
        }
        asm volatile("cp.async.commit_group;\n");
    };

    load_chunk(0);
    load_chunk(1);

#pragma unroll 1
    for (int kt = 0; kt < 16; kt++) {
        if (kt < 15) asm volatile("cp.async.wait_group 1;\n");
        else         asm volatile("cp.async.wait_group 0;\n");
        __syncthreads();   // orders last iteration's LDSM reads before the overwrite below

        if (kt + 2 < 16) load_chunk(kt + 2);   // overwrites stage (kt-1)%3 — safe after sync

        const uint32_t ab = sbase + (kt % NSTG) * STG_BYTES;
        const uint32_t bb = ab + OPER_BYTES;
#pragma unroll
        for (int ks = 0; ks < 4; ks++) {
            const int kb = ks * 16;
            unsigned av[2][4];
#pragma unroll
            for (int i = 0; i < 2; i++) {
                uint32_t off = (uint32_t)(wm * 32 + i * 16 + rA) * 128 + (kb + cA) * 2;
                asm volatile("ldmatrix.sync.aligned.m8n8.x4.shared.b16 {%0,%1,%2,%3}, [%4];"
                             : "=r"(av[i][0]), "=r"(av[i][1]), "=r"(av[i][2]), "=r"(av[i][3])
                             : "r"(ab + SW(off)));
            }
#pragma unroll
            for (int jj = 0; jj < 4; jj++) {
                unsigned bv[4];
                uint32_t off = (uint32_t)(wn * 64 + jj * 16 + rB) * 128 + (kb + cB) * 2;
                asm volatile("ldmatrix.sync.aligned.m8n8.x4.shared.b16 {%0,%1,%2,%3}, [%4];"
                             : "=r"(bv[0]), "=r"(bv[1]), "=r"(bv[2]), "=r"(bv[3])
                             : "r"(bb + SW(off)));
#pragma unroll
                for (int jh = 0; jh < 2; jh++) {
                    int j = jj * 2 + jh;
#pragma unroll
                    for (int i = 0; i < 2; i++) {
                        asm volatile(
                            "mma.sync.aligned.m16n8k16.row.col.f32.bf16.bf16.f32 "
                            "{%0,%1,%2,%3}, {%4,%5,%6,%7}, {%8,%9}, {%0,%1,%2,%3};"
                            : "+f"(acc[i][j][0]), "+f"(acc[i][j][1]),
                              "+f"(acc[i][j][2]), "+f"(acc[i][j][3])
                            : "r"(av[i][0]), "r"(av[i][1]), "r"(av[i][2]), "r"(av[i][3]),
                              "r"(bv[jh * 2]), "r"(bv[jh * 2 + 1]));
                    }
                }
            }
        }
    }

    // epilogue: dequant per token + bias (float2 stores)
#pragma unroll
    for (int i = 0; i < 2; i++) {
        long row = arow0 + wm * 32 + i * 16 + g;
        float r0 = g_arecip[row];
        float r1 = g_arecip[row + 8];
#pragma unroll
        for (int j = 0; j < 8; j++) {
            int col = brow0 + wn * 64 + j * 8 + 2 * tg;
            float b0v = bias[col], b1v = bias[col + 1];
            float2 lo = make_float2(acc[i][j][0] * r0 + b0v, acc[i][j][1] * r0 + b1v);
            float2 hi = make_float2(acc[i][j][2] * r1 + b0v, acc[i][j][3] * r1 + b1v);
            *(float2*)(out + row * ODIM + col)       = lo;
            *(float2*)(out + (row + 8) * ODIM + col) = hi;
        }
    }
}

// ---------------- launch ----------------
extern "C" void kernel_launch(void* const* d_in, const int* in_sizes, int n_in,
                              void* d_out, int out_size) {
    const float* x        = (const float*)d_in[0];
    const float* c        = (const float*)d_in[1];
    const float* w_input  = (const float*)d_in[2];
    const float* w_gate   = (const float*)d_in[3];
    const float* w_down   = (const float*)d_in[4];
    const float* w_output = (const float*)d_in[5];
    const float* b_output = (const float*)d_in[6];
    const float* w_norm   = (const float*)d_in[7];
    const float* w_outp   = (const float*)d_in[8];
    const float* b_outp   = (const float*)d_in[9];
    const float* w_bit    = (const float*)d_in[10];
    const float* b_bit    = (const float*)d_in[11];
    const float* w_bn     = (const float*)d_in[12];
    float* out = (float*)d_out;

    float *p_h, *p_u, *p_z, *p_o, *p_mod;
    cudaGetSymbolAddress((void**)&p_h,   g_h);
    cudaGetSymbolAddress((void**)&p_u,   g_u);
    cudaGetSymbolAddress((void**)&p_z,   g_z);
    cudaGetSymbolAddress((void**)&p_o,   g_o);
    cudaGetSymbolAddress((void**)&p_mod, g_mod);

    // weight quant path (independent)
    wabs_partial_kernel<<<1024, 256>>>(w_bit);
    wabs_final_kernel<<<1, 256>>>();
    wquant_kernel<<<(ODIM * HID / 4) / 256, 256>>>(w_bit);

    // modulation chain (B=4) — silu fused into input proj; gate pair fused
    gemm4_silu_kernel<<<512, 256>>>(c, w_input, p_h, HID, HID);
    gemm4gate_kernel<<<1408, 256>>>(p_h, w_gate, p_u);
    gemm4_kernel<<<512, 256>>>(p_u, w_down, nullptr, p_z, INTERD, HID);
    gemm4_kernel<<<1024, 256>>>(p_z, w_output, b_output, p_o, HID, 2 * HID);
    rms4_kernel<<<4, 256>>>(w_norm);
    gemm4_kernel<<<1024, 256>>>(p_o, w_outp, b_outp, p_mod, 2 * HID, 2 * HID);

    // per-token normalize + bf16-int quantize (shuffle reductions)
    aq_kernel<<<NTOK, 256>>>(x, w_bn);

    // main GEMM: R11 config (128x128 tiles, 256 threads, 3-stage, 96KB smem, 2 CTA/SM)
    static const int smem_bytes = NSTG * STG_BYTES;   // 98304
    cudaFuncSetAttribute(bitgemm_kernel, cudaFuncAttributeMaxDynamicSharedMemorySize, smem_bytes);
    dim3 ggrid(8, 256);   // n-tiles fastest: 8 column tiles share the A m-tile via L2
    bitgemm_kernel<<<ggrid, 256, smem_bytes>>>(b_bit, out);
}

// round 14
// speedup vs baseline: 1.0390x; 1.0065x over previous
#include <cuda_runtime.h>
#include <cuda_bf16.h>
#include <cstdint>

#define HID    1024
#define INTERD 2816
#define BB     4
#define NTOK   32768   // B * N = 4 * 8192
#define ODIM   1024

// ---------------- scratch (static device globals; no allocs) ----------------
__device__ float g_h[BB * HID];
__device__ float g_u[BB * INTERD];
__device__ float g_z[BB * HID];
__device__ float g_o[BB * 2 * HID];
__device__ float g_mod[BB * 2 * HID];
__device__ float g_part[1024];
__device__ float g_ws[2];                              // [0]=1/clip(mean|w|), [1]=clip(mean|w|)
__device__ __align__(16) __nv_bfloat16 g_wq[(long)ODIM * HID];   // ternary weights bf16
__device__ __align__(16) __nv_bfloat16 g_q[(long)NTOK * HID];    // quantized activations bf16 (ints)
__device__ float g_arecip[NTOK];                       // amax/127 * mean|w|

__device__ __forceinline__ float silu_f(float v) { return v / (1.f + expf(-v)); }

// ---------------- modulation chain kernels ----------------
// h[b,d] = sum_k silu(c[b,k]) * W[d,k]
__global__ void gemm4_silu_kernel(const float* __restrict__ C, const float* __restrict__ W,
                                  float* __restrict__ out, int K, int D) {
    int warp = threadIdx.x >> 5, lane = threadIdx.x & 31;
    int idx = blockIdx.x * 8 + warp;
    if (idx >= 4 * D) return;
    int b = idx / D, d = idx - b * D;
    const float4* a = (const float4*)(C + (long)b * K);
    const float4* w = (const float4*)(W + (long)d * K);
    int K4 = K >> 2;
    float s = 0.f;
#pragma unroll 8
    for (int k = lane; k < K4; k += 32) {
        float4 av = a[k], wv = w[k];
        s += silu_f(av.x) * wv.x + silu_f(av.y) * wv.y
           + silu_f(av.z) * wv.z + silu_f(av.w) * wv.w;
    }
#pragma unroll
    for (int o = 16; o; o >>= 1) s += __shfl_xor_sync(0xffffffffu, s, o);
    if (lane == 0) out[idx] = s;
}

// u[b,j] = silu(h.w_gate[j]) * (h.w_gate[INTER+j])
__global__ void gemm4gate_kernel(const float* __restrict__ A, const float* __restrict__ W,
                                 float* __restrict__ out) {
    int warp = threadIdx.x >> 5, lane = threadIdx.x & 31;
    int idx = blockIdx.x * 8 + warp;
    if (idx >= 4 * INTERD) return;
    int b = idx / INTERD, j = idx - b * INTERD;
    const float4* a  = (const float4*)(A + (long)b * HID);
    const float4* wg = (const float4*)(W + (long)j * HID);
    const float4* wy = (const float4*)(W + (long)(INTERD + j) * HID);
    float sg = 0.f, sy = 0.f;
#pragma unroll 8
    for (int k = lane; k < HID / 4; k += 32) {
        float4 av = a[k];
        float4 g = wg[k], y = wy[k];
        sg += av.x*g.x + av.y*g.y + av.z*g.z + av.w*g.w;
        sy += av.x*y.x + av.y*y.y + av.z*y.z + av.w*y.w;
    }
#pragma unroll
    for (int o = 16; o; o >>= 1) {
        sg += __shfl_xor_sync(0xffffffffu, sg, o);
        sy += __shfl_xor_sync(0xffffffffu, sy, o);
    }
    if (lane == 0) out[idx] = silu_f(sg) * sy;
}

// out[b,d] = sum_k A[b,k]*W[d,k] (+bias[d])
__global__ void gemm4_kernel(const float* __restrict__ A, const float* __restrict__ W,
                             const float* __restrict__ bias, float* __restrict__ out,
                             int K, int D) {
    int warp = threadIdx.x >> 5, lane = threadIdx.x & 31;
    int idx = blockIdx.x * 8 + warp;
    if (idx >= 4 * D) return;
    int b = idx / D, d = idx - b * D;
    const float4* a = (const float4*)(A + (long)b * K);
    const float4* w = (const float4*)(W + (long)d * K);
    int K4 = K >> 2;
    float s = 0.f;
#pragma unroll 8
    for (int k = lane; k < K4; k += 32) {
        float4 av = a[k], wv = w[k];
        s += av.x * wv.x + av.y * wv.y + av.z * wv.z + av.w * wv.w;
    }
#pragma unroll
    for (int o = 16; o; o >>= 1) s += __shfl_xor_sync(0xffffffffu, s, o);
    if (lane == 0) out[idx] = s + (bias ? bias[d] : 0.f);
}

// mod[b,d] = rstd_b * (sum_k o[b,k]*wn[k]*W[d,k]) + bias[d],
// rstd_b = rsqrt(mean(o[b,:]^2) + 1e-6)  — rmsnorm fused into the projection.
__global__ void gemm4_rms_kernel(const float* __restrict__ W, const float* __restrict__ bias,
                                 const float* __restrict__ wn, float* __restrict__ out) {
    const int K = 2048, D = 2048;
    int warp = threadIdx.x >> 5, lane = threadIdx.x & 31;
    int idx = blockIdx.x * 8 + warp;
    if (idx >= 4 * D) return;
    int b = idx / D, d = idx - b * D;
    const float4* a  = (const float4*)(g_o + (long)b * K);
    const float4* wv4 = (const float4*)(W + (long)d * K);
    const float4* wn4 = (const float4*)wn;
    float s = 0.f, s2 = 0.f;
#pragma unroll 8
    for (int k = lane; k < K / 4; k += 32) {
        float4 av = a[k], wv = wv4[k], nv = wn4[k];
        s  += av.x*nv.x*wv.x + av.y*nv.y*wv.y + av.z*nv.z*wv.z + av.w*nv.w*wv.w;
        s2 += av.x*av.x + av.y*av.y + av.z*av.z + av.w*av.w;
    }
#pragma unroll
    for (int o = 16; o; o >>= 1) {
        s  += __shfl_xor_sync(0xffffffffu, s, o);
        s2 += __shfl_xor_sync(0xffffffffu, s2, o);
    }
    if (lane == 0) {
        float rstd = rsqrtf(s2 * (1.f / 2048.f) + 1e-6f);
        out[idx] = s * rstd + bias[d];
    }
}

// ---------------- weight quant (deterministic reduction) ----------------
__global__ void wabs_partial_kernel(const float* __restrict__ w) {
    __shared__ float sm[256];
    int b = blockIdx.x, tid = threadIdx.x;
    const float* p = w + (long)b * 1024;
    float s = 0.f;
    for (int i = tid; i < 1024; i += 256) s += fabsf(p[i]);
    sm[tid] = s; __syncthreads();
    for (int st = 128; st > 0; st >>= 1) { if (tid < st) sm[tid] += sm[tid + st]; __syncthreads(); }
    if (tid == 0) g_part[b] = sm[0];
}

// merged final-reduce + quant: every block redundantly computes the IDENTICAL
// deterministic reduction of g_part (same order -> same value), block 0 publishes g_ws.
__global__ void wquant_kernel(const float* __restrict__ w) {
    __shared__ float sm[256];
    int tid = threadIdx.x;
    float s = g_part[tid] + g_part[tid + 256] + g_part[tid + 512] + g_part[tid + 768];
    sm[tid] = s; __syncthreads();
    for (int st = 128; st > 0; st >>= 1) { if (tid < st) sm[tid] += sm[tid + st]; __syncthreads(); }
    float mean = sm[0] * (1.f / (1024.f * 1024.f));
    float m = fmaxf(mean, 1e-5f);
    float scale = 1.f / m;
    if (blockIdx.x == 0 && tid == 0) { g_ws[0] = scale; g_ws[1] = m; }
    int i = blockIdx.x * 256 + tid;                   // groups of 4
    if (i < ODIM * HID / 4) {
        const float4 v = ((const float4*)w)[i];
        __nv_bfloat162 lo, hi;
        lo.x = __float2bfloat16(fminf(fmaxf(rintf(v.x * scale), -1.f), 1.f));
        lo.y = __float2bfloat16(fminf(fmaxf(rintf(v.y * scale), -1.f), 1.f));
        hi.x = __float2bfloat16(fminf(fmaxf(rintf(v.z * scale), -1.f), 1.f));
        hi.y = __float2bfloat16(fminf(fmaxf(rintf(v.w * scale), -1.f), 1.f));
        ((__nv_bfloat162*)g_wq)[i * 2]     = lo;
        ((__nv_bfloat162*)g_wq)[i * 2 + 1] = hi;
    }
}

// ---------------- activation pipeline: LN -> modulate -> RMSNorm -> quant ----------------
__global__ void aq_kernel(const float* __restrict__ x, const float* __restrict__ wbn) {
    __shared__ float p1[8], p2[8];
    int t = blockIdx.x, tid = threadIdx.x;
    int wid = tid >> 5, lane = tid & 31;
    int b = t >> 13;
    const float4* xr = (const float4*)(x + (long)t * HID);
    const float* mod = g_mod + b * 2048;              // [0:1024) shift, [1024:2048) scale
    float4 v = xr[tid];

    float s = v.x + v.y + v.z + v.w;
    float s2 = v.x*v.x + v.y*v.y + v.z*v.z + v.w*v.w;
#pragma unroll
    for (int o = 16; o; o >>= 1) {
        s  += __shfl_xor_sync(0xffffffffu, s, o);
        s2 += __shfl_xor_sync(0xffffffffu, s2, o);
    }
    if (lane == 0) { p1[wid] = s; p2[wid] = s2; }
    __syncthreads();
    float S = 0.f, S2 = 0.f;
#pragma unroll
    for (int i = 0; i < 8; i++) { S += p1[i]; S2 += p2[i]; }
    float mean = S * (1.f / HID);
    float var = S2 * (1.f / HID) - mean * mean;
    float rstd = rsqrtf(var + 1e-6f);
    __syncthreads();

    int h0 = tid * 4;
    v.x = (v.x - mean) * rstd * (1.f + mod[1024+h0])   + mod[h0];
    v.y = (v.y - mean) * rstd * (1.f + mod[1024+h0+1]) + mod[h0+1];
    v.z = (v.z - mean) * rstd * (1.f + mod[1024+h0+2]) + mod[h0+2];
    v.w = (v.w - mean) * rstd * (1.f + mod[1024+h0+3]) + mod[h0+3];
    float ms = v.x*v.x + v.y*v.y + v.z*v.z + v.w*v.w;
#pragma unroll
    for (int o = 16; o; o >>= 1) ms += __shfl_xor_sync(0xffffffffu, ms, o);
    if (lane == 0) p1[wid] = ms;
    __syncthreads();
    float MS = 0.f;
#pragma unroll
    for (int i = 0; i < 8; i++) MS += p1[i];
    float rr = rsqrtf(MS * (1.f / HID) + 1e-8f);
    __syncthreads();

    v.x *= rr * wbn[h0];   v.y *= rr * wbn[h0+1];
    v.z *= rr * wbn[h0+2]; v.w *= rr * wbn[h0+3];
    float amax = fmaxf(fmaxf(fabsf(v.x), fabsf(v.y)), fmaxf(fabsf(v.z), fabsf(v.w)));
#pragma unroll
    for (int o = 16; o; o >>= 1) amax = fmaxf(amax, __shfl_xor_sync(0xffffffffu, amax, o));
    if (lane == 0) p1[wid] = amax;
    __syncthreads();
    float AM = 0.f;
#pragma unroll
    for (int i = 0; i < 8; i++) AM = fmaxf(AM, p1[i]);
    float am = fmaxf(AM, 1e-5f);
    float sa = 127.f / am;

    __nv_bfloat162 q0, q1;
    q0.x = __float2bfloat16(fminf(fmaxf(rintf(v.x * sa), -128.f), 127.f));
    q0.y = __float2bfloat16(fminf(fmaxf(rintf(v.y * sa), -128.f), 127.f));
    q1.x = __float2bfloat16(fminf(fmaxf(rintf(v.z * sa), -128.f), 127.f));
    q1.y = __float2bfloat16(fminf(fmaxf(rintf(v.w * sa), -128.f), 127.f));
    __nv_bfloat162* qp = (__nv_bfloat162*)(g_q + (long)t * HID);
    qp[tid * 2]     = q0;
    qp[tid * 2 + 1] = q1;
    if (tid == 0) g_arecip[t] = am * (1.f / 127.f) * g_ws[1];
}

// ---------------- main GEMM: R11 config — 128x128 tile, 256 threads, 2 CTA/SM ----------------
__device__ __forceinline__ void cp16s(uint32_t saddr, const void* g) {
    asm volatile("cp.async.cg.shared.global [%0], [%1], 16;\n" :: "r"(saddr), "l"(g));
}

#define NSTG       3
#define OPER_BYTES 16384            // 128 rows x 128 B (one operand, one stage)
#define STG_BYTES  32768            // A + B per stage
#define SW(o) ((o) ^ (((o) >> 3) & 0x70))

extern __shared__ __align__(16) char smdyn[];

__global__ void __launch_bounds__(256, 2) bitgemm_kernel(const float* __restrict__ bias,
                                                         float* __restrict__ out) {
    const int tid = threadIdx.x;
    const int lane = tid & 31, warp = tid >> 5;
    const int wm = warp >> 1, wn = warp & 1;      // 4x2 warp grid: 32 rows x 64 cols per warp
    const long arow0 = (long)blockIdx.y * 128;
    const int brow0 = blockIdx.x * 128;
    const int g = lane >> 2, tg = lane & 3;

    uint32_t sbase;
    asm("{ .reg .u64 t; cvta.to.shared.u64 t, %1; cvt.u32.u64 %0, t; }"
        : "=r"(sbase) : "l"(smdyn));

    const int lr = lane & 7, blk = lane >> 3;
    const int rA = lr + (blk & 1) * 8, cA = (blk >> 1) * 8;
    const int rB = lr + (blk >> 1) * 8, cB = (blk & 1) * 8;

    float acc[2][8][4];
#pragma unroll
    for (int i = 0; i < 2; i++)
#pragma unroll
        for (int j = 0; j < 8; j++)
#pragma unroll
            for (int r = 0; r < 4; r++) acc[i][j][r] = 0.f;

    auto load_chunk = [&](int kt) {
        const uint32_t ab = sbase + (kt % NSTG) * STG_BYTES;
        const uint32_t bb = ab + OPER_BYTES;
        const int k0 = kt * 64;
#pragma unroll
        for (int it = 0; it < 4; it++) {
            int idx = it * 256 + tid;
            int row = idx >> 3, u = idx & 7;
            uint32_t off = row * 128 + u * 16;
            cp16s(ab + SW(off), g_q + (arow0 + row) * HID + k0 + u * 8);
            cp16s(bb + SW(off), g_wq + (long)(brow0 + row) * HID + k0 + u * 8);
        }
        asm volatile("cp.async.commit_group;\n");
    };

    load_chunk(0);
    load_chunk(1);

#pragma unroll 1
    for (int kt = 0; kt < 16; kt++) {
        if (kt < 15) asm volatile("cp.async.wait_group 1;\n");
        else         asm volatile("cp.async.wait_group 0;\n");
        __syncthreads();

        if (kt + 2 < 16) load_chunk(kt + 2);

        const uint32_t ab = sbase + (kt % NSTG) * STG_BYTES;
        const uint32_t bb = ab + OPER_BYTES;
#pragma unroll
        for (int ks = 0; ks < 4; ks++) {
            const int kb = ks * 16;
            unsigned av[2][4];
#pragma unroll
            for (int i = 0; i < 2; i++) {
                uint32_t off = (uint32_t)(wm * 32 + i * 16 + rA) * 128 + (kb + cA) * 2;
                asm volatile("ldmatrix.sync.aligned.m8n8.x4.shared.b16 {%0,%1,%2,%3}, [%4];"
                             : "=r"(av[i][0]), "=r"(av[i][1]), "=r"(av[i][2]), "=r"(av[i][3])
                             : "r"(ab + SW(off)));
            }
#pragma unroll
            for (int jj = 0; jj < 4; jj++) {
                unsigned bv[4];
                uint32_t off = (uint32_t)(wn * 64 + jj * 16 + rB) * 128 + (kb + cB) * 2;
                asm volatile("ldmatrix.sync.aligned.m8n8.x4.shared.b16 {%0,%1,%2,%3}, [%4];"
                             : "=r"(bv[0]), "=r"(bv[1]), "=r"(bv[2]), "=r"(bv[3])
                             : "r"(bb + SW(off)));
#pragma unroll
                for (int jh = 0; jh < 2; jh++) {
                    int j = jj * 2 + jh;
#pragma unroll
                    for (int i = 0; i < 2; i++) {
                        asm volatile(
                            "mma.sync.aligned.m16n8k16.row.col.f32.bf16.bf16.f32 "
                            "{%0,%1,%2,%3}, {%4,%5,%6,%7}, {%8,%9}, {%0,%1,%2,%3};"
                            : "+f"(acc[i][j][0]), "+f"(acc[i][j][1]),
                              "+f"(acc[i][j][2]), "+f"(acc[i][j][3])
                            : "r"(av[i][0]), "r"(av[i][1]), "r"(av[i][2]), "r"(av[i][3]),
                              "r"(bv[jh * 2]), "r"(bv[jh * 2 + 1]));
                    }
                }
            }
        }
    }

#pragma unroll
    for (int i = 0; i < 2; i++) {
        long row = arow0 + wm * 32 + i * 16 + g;
        float r0 = g_arecip[row];
        float r1 = g_arecip[row + 8];
#pragma unroll
        for (int j = 0; j < 8; j++) {
            int col = brow0 + wn * 64 + j * 8 + 2 * tg;
            float b0v = bias[col], b1v = bias[col + 1];
            float2 lo = make_float2(acc[i][j][0] * r0 + b0v, acc[i][j][1] * r0 + b1v);
            float2 hi = make_float2(acc[i][j][2] * r1 + b0v, acc[i][j][3] * r1 + b1v);
            *(float2*)(out + row * ODIM + col)       = lo;
            *(float2*)(out + (row + 8) * ODIM + col) = hi;
        }
    }
}

// ---------------- launch ----------------
extern "C" void kernel_launch(void* const* d_in, const int* in_sizes, int n_in,
                              void* d_out, int out_size) {
    const float* x        = (const float*)d_in[0];
    const float* c        = (const float*)d_in[1];
    const float* w_input  = (const float*)d_in[2];
    const float* w_gate   = (const float*)d_in[3];
    const float* w_down   = (const float*)d_in[4];
    const float* w_output = (const float*)d_in[5];
    const float* b_output = (const float*)d_in[6];
    const float* w_norm   = (const float*)d_in[7];
    const float* w_outp   = (const float*)d_in[8];
    const float* b_outp   = (const float*)d_in[9];
    const float* w_bit    = (const float*)d_in[10];
    const float* b_bit    = (const float*)d_in[11];
    const float* w_bn     = (const float*)d_in[12];
    float* out = (float*)d_out;

    float *p_h, *p_u, *p_z, *p_o, *p_mod;
    cudaGetSymbolAddress((void**)&p_h,   g_h);
    cudaGetSymbolAddress((void**)&p_u,   g_u);
    cudaGetSymbolAddress((void**)&p_z,   g_z);
    cudaGetSymbolAddress((void**)&p_o,   g_o);
    cudaGetSymbolAddress((void**)&p_mod, g_mod);

    // weight quant path: partial reduce, then merged final-reduce + quant
    wabs_partial_kernel<<<1024, 256>>>(w_bit);
    wquant_kernel<<<(ODIM * HID / 4) / 256, 256>>>(w_bit);

    // modulation chain (B=4): silu fused; gate pair fused; rmsnorm fused into out-proj
    gemm4_silu_kernel<<<512, 256>>>(c, w_input, p_h, HID, HID);
    gemm4gate_kernel<<<1408, 256>>>(p_h, w_gate, p_u);
    gemm4_kernel<<<512, 256>>>(p_u, w_down, nullptr, p_z, INTERD, HID);
    gemm4_kernel<<<1024, 256>>>(p_z, w_output, b_output, p_o, HID, 2 * HID);
    gemm4_rms_kernel<<<1024, 256>>>(w_outp, b_outp, w_norm, p_mod);

    // per-token normalize + bf16-int quantize
    aq_kernel<<<NTOK, 256>>>(x, w_bn);

    // main GEMM (proven R11 config)
    static const int smem_bytes = NSTG * STG_BYTES;   // 98304
    cudaFuncSetAttribute(bitgemm_kernel, cudaFuncAttributeMaxDynamicSharedMemorySize, smem_bytes);
    dim3 ggrid(8, 256);
    bitgemm_kernel<<<ggrid, 256, smem_bytes>>>(b_bit, out);
}

// round 17
// speedup vs baseline: 1.0457x; 1.0065x over previous
#include <cuda_runtime.h>
#include <cuda_bf16.h>
#include <cstdint>

#define HID    1024
#define INTERD 2816
#define BB     4
#define NTOK   32768   // B * N = 4 * 8192
#define ODIM   1024

// ---------------- scratch (static device globals; no allocs) ----------------
__device__ float g_h[BB * HID];
__device__ float g_u[BB * INTERD];
__device__ float g_z[BB * HID];
__device__ float g_o[BB * 2 * HID];
__device__ float g_mod[BB * 2 * HID];
__device__ float g_part[1024];
__device__ float g_ws[2];                              // [0]=1/clip(mean|w|), [1]=clip(mean|w|)
__device__ __align__(16) __nv_bfloat16 g_wq[(long)ODIM * HID];   // ternary weights bf16
__device__ __align__(16) __nv_bfloat16 g_q[(long)NTOK * HID];    // quantized activations bf16 (ints)
__device__ float g_arecip[NTOK];                       // amax/127 * mean|w|

__device__ __forceinline__ float silu_f(float v) { return v / (1.f + expf(-v)); }

// ---------------- modulation chain kernels ----------------
// h[b,d] = sum_k silu(c[b,k]) * W[d,k]
__global__ void gemm4_silu_kernel(const float* __restrict__ C, const float* __restrict__ W,
                                  float* __restrict__ out, int K, int D) {
    int warp = threadIdx.x >> 5, lane = threadIdx.x & 31;
    int idx = blockIdx.x * 8 + warp;
    if (idx >= 4 * D) return;
    int b = idx / D, d = idx - b * D;
    const float4* a = (const float4*)(C + (long)b * K);
    const float4* w = (const float4*)(W + (long)d * K);
    int K4 = K >> 2;
    float s = 0.f;
#pragma unroll 8
    for (int k = lane; k < K4; k += 32) {
        float4 av = a[k], wv = w[k];
        s += silu_f(av.x) * wv.x + silu_f(av.y) * wv.y
           + silu_f(av.z) * wv.z + silu_f(av.w) * wv.w;
    }
#pragma unroll
    for (int o = 16; o; o >>= 1) s += __shfl_xor_sync(0xffffffffu, s, o);
    if (lane == 0) out[idx] = s;
}

// u[{2p,2p+1},j] = silu(h.wg[j]) * (h.wy[j]) for a batch PAIR — weights loaded once per pair.
__global__ void gemm4gate_kernel(const float* __restrict__ A, const float* __restrict__ W,
                                 float* __restrict__ out) {
    int warp = threadIdx.x >> 5, lane = threadIdx.x & 31;
    int idx = blockIdx.x * 8 + warp;                  // [0, 2*INTERD)
    if (idx >= 2 * INTERD) return;
    int p = idx / INTERD, j = idx - p * INTERD;       // p = batch pair (0 or 1)
    const float4* a0 = (const float4*)(A + (long)(2 * p)     * HID);
    const float4* a1 = (const float4*)(A + (long)(2 * p + 1) * HID);
    const float4* wg = (const float4*)(W + (long)j * HID);
    const float4* wy = (const float4*)(W + (long)(INTERD + j) * HID);
    float sg0 = 0.f, sy0 = 0.f, sg1 = 0.f, sy1 = 0.f;
#pragma unroll 8
    for (int k = lane; k < HID / 4; k += 32) {
        float4 g = wg[k], y = wy[k];
        float4 v0 = a0[k], v1 = a1[k];
        sg0 += v0.x*g.x + v0.y*g.y + v0.z*g.z + v0.w*g.w;
        sy0 += v0.x*y.x + v0.y*y.y + v0.z*y.z + v0.w*y.w;
        sg1 += v1.x*g.x + v1.y*g.y + v1.z*g.z + v1.w*g.w;
        sy1 += v1.x*y.x + v1.y*y.y + v1.z*y.z + v1.w*y.w;
    }
#pragma unroll
    for (int o = 16; o; o >>= 1) {
        sg0 += __shfl_xor_sync(0xffffffffu, sg0, o);
        sy0 += __shfl_xor_sync(0xffffffffu, sy0, o);
        sg1 += __shfl_xor_sync(0xffffffffu, sg1, o);
        sy1 += __shfl_xor_sync(0xffffffffu, sy1, o);
    }
    if (lane == 0) {
        out[(long)(2 * p) * INTERD + j]     = silu_f(sg0) * sy0;
        out[(long)(2 * p + 1) * INTERD + j] = silu_f(sg1) * sy1;
    }
}

// out[b,d] = sum_k A[b,k]*W[d,k] (+bias[d])
__global__ void gemm4_kernel(const float* __restrict__ A, const float* __restrict__ W,
                             const float* __restrict__ bias, float* __restrict__ out,
                             int K, int D) {
    int warp = threadIdx.x >> 5, lane = threadIdx.x & 31;
    int idx = blockIdx.x * 8 + warp;
    if (idx >= 4 * D) return;
    int b = idx / D, d = idx - b * D;
    const float4* a = (const float4*)(A + (long)b * K);
    const float4* w = (const float4*)(W + (long)d * K);
    int K4 = K >> 2;
    float s = 0.f;
#pragma unroll 8
    for (int k = lane; k < K4; k += 32) {
        float4 av = a[k], wv = w[k];
        s += av.x * wv.x + av.y * wv.y + av.z * wv.z + av.w * wv.w;
    }
#pragma unroll
    for (int o = 16; o; o >>= 1) s += __shfl_xor_sync(0xffffffffu, s, o);
    if (lane == 0) out[idx] = s + (bias ? bias[d] : 0.f);
}

// mod[b,{d,d+1}] = rstd_b * (sum_k o[b,k]*wn[k]*W[{d,d+1},k]) + bias — 2 outputs/warp,
// o-row and wn loaded once for both.
__global__ void gemm4_rms_kernel(const float* __restrict__ W, const float* __restrict__ bias,
                                 const float* __restrict__ wn, float* __restrict__ out) {
    const int K = 2048, D = 2048;
    int warp = threadIdx.x >> 5, lane = threadIdx.x & 31;
    int pidx = blockIdx.x * 8 + warp;                 // [0, 4*D/2)
    if (pidx >= 4 * D / 2) return;
    int b = pidx / (D / 2), d = (pidx - b * (D / 2)) * 2;
    const float4* a   = (const float4*)(g_o + (long)b * K);
    const float4* w0  = (const float4*)(W + (long)d * K);
    const float4* w1  = (const float4*)(W + (long)(d + 1) * K);
    const float4* wn4 = (const float4*)wn;
    float s0 = 0.f, s1 = 0.f, s2 = 0.f;
#pragma unroll 8
    for (int k = lane; k < K / 4; k += 32) {
        float4 av = a[k], nv = wn4[k];
        float4 m = make_float4(av.x * nv.x, av.y * nv.y, av.z * nv.z, av.w * nv.w);
        float4 v0 = w0[k], v1 = w1[k];
        s0 += m.x*v0.x + m.y*v0.y + m.z*v0.z + m.w*v0.w;
        s1 += m.x*v1.x + m.y*v1.y + m.z*v1.z + m.w*v1.w;
        s2 += av.x*av.x + av.y*av.y + av.z*av.z + av.w*av.w;
    }
#pragma unroll
    for (int o = 16; o; o >>= 1) {
        s0 += __shfl_xor_sync(0xffffffffu, s0, o);
        s1 += __shfl_xor_sync(0xffffffffu, s1, o);
        s2 += __shfl_xor_sync(0xffffffffu, s2, o);
    }
    if (lane == 0) {
        float rstd = rsqrtf(s2 * (1.f / 2048.f) + 1e-6f);
        out[(long)b * D + d]     = s0 * rstd + bias[d];
        out[(long)b * D + d + 1] = s1 * rstd + bias[d + 1];
    }
}

// ---------------- weight quant (deterministic reduction) ----------------
__global__ void wabs_partial_kernel(const float* __restrict__ w) {
    __shared__ float sm[256];
    int b = blockIdx.x, tid = threadIdx.x;
    const float* p = w + (long)b * 1024;
    float s = 0.f;
    for (int i = tid; i < 1024; i += 256) s += fabsf(p[i]);
    sm[tid] = s; __syncthreads();
    for (int st = 128; st > 0; st >>= 1) { if (tid < st) sm[tid] += sm[tid + st]; __syncthreads(); }
    if (tid == 0) g_part[b] = sm[0];
}

// merged final-reduce + quant (every block redoes the identical deterministic reduction)
__global__ void wquant_kernel(const float* __restrict__ w) {
    __shared__ float sm[256];
    int tid = threadIdx.x;
    float s = g_part[tid] + g_part[tid + 256] + g_part[tid + 512] + g_part[tid + 768];
    sm[tid] = s; __syncthreads();
    for (int st = 128; st > 0; st >>= 1) { if (tid < st) sm[tid] += sm[tid + st]; __syncthreads(); }
    float mean = sm[0] * (1.f / (1024.f * 1024.f));
    float m = fmaxf(mean, 1e-5f);
    float scale = 1.f / m;
    if (blockIdx.x == 0 && tid == 0) { g_ws[0] = scale; g_ws[1] = m; }
    int i = blockIdx.x * 256 + tid;                   // groups of 4
    if (i < ODIM * HID / 4) {
        const float4 v = ((const float4*)w)[i];
        __nv_bfloat162 lo, hi;
        lo.x = __float2bfloat16(fminf(fmaxf(rintf(v.x * scale), -1.f), 1.f));
        lo.y = __float2bfloat16(fminf(fmaxf(rintf(v.y * scale), -1.f), 1.f));
        hi.x = __float2bfloat16(fminf(fmaxf(rintf(v.z * scale), -1.f), 1.f));
        hi.y = __float2bfloat16(fminf(fmaxf(rintf(v.w * scale), -1.f), 1.f));
        ((__nv_bfloat162*)g_wq)[i * 2]     = lo;
        ((__nv_bfloat162*)g_wq)[i * 2 + 1] = hi;
    }
}

// ---------------- activation pipeline: LN -> modulate -> RMSNorm -> quant ----------------
__global__ void aq_kernel(const float* __restrict__ x, const float* __restrict__ wbn) {
    __shared__ float p1[8], p2[8];
    int t = blockIdx.x, tid = threadIdx.x;
    int wid = tid >> 5, lane = tid & 31;
    int b = t >> 13;
    const float4* xr = (const float4*)(x + (long)t * HID);
    const float* mod = g_mod + b * 2048;              // [0:1024) shift, [1024:2048) scale
    float4 v = xr[tid];

    float s = v.x + v.y + v.z + v.w;
    float s2 = v.x*v.x + v.y*v.y + v.z*v.z + v.w*v.w;
#pragma unroll
    for (int o = 16; o; o >>= 1) {
        s  += __shfl_xor_sync(0xffffffffu, s, o);
        s2 += __shfl_xor_sync(0xffffffffu, s2, o);
    }
    if (lane == 0) { p1[wid] = s; p2[wid] = s2; }
    __syncthreads();
    float S = 0.f, S2 = 0.f;
#pragma unroll
    for (int i = 0; i < 8; i++) { S += p1[i]; S2 += p2[i]; }
    float mean = S * (1.f / HID);
    float var = S2 * (1.f / HID) - mean * mean;
    float rstd = rsqrtf(var + 1e-6f);
    __syncthreads();

    int h0 = tid * 4;
    v.x = (v.x - mean) * rstd * (1.f + mod[1024+h0])   + mod[h0];
    v.y = (v.y - mean) * rstd * (1.f + mod[1024+h0+1]) + mod[h0+1];
    v.z = (v.z - mean) * rstd * (1.f + mod[1024+h0+2]) + mod[h0+2];
    v.w = (v.w - mean) * rstd * (1.f + mod[1024+h0+3]) + mod[h0+3];
    float ms = v.x*v.x + v.y*v.y + v.z*v.z + v.w*v.w;
#pragma unroll
    for (int o = 16; o; o >>= 1) ms += __shfl_xor_sync(0xffffffffu, ms, o);
    if (lane == 0) p1[wid] = ms;
    __syncthreads();
    float MS = 0.f;
#pragma unroll
    for (int i = 0; i < 8; i++) MS += p1[i];
    float rr = rsqrtf(MS * (1.f / HID) + 1e-8f);
    __syncthreads();

    v.x *= rr * wbn[h0];   v.y *= rr * wbn[h0+1];
    v.z *= rr * wbn[h0+2]; v.w *= rr * wbn[h0+3];
    float amax = fmaxf(fmaxf(fabsf(v.x), fabsf(v.y)), fmaxf(fabsf(v.z), fabsf(v.w)));
#pragma unroll
    for (int o = 16; o; o >>= 1) amax = fmaxf(amax, __shfl_xor_sync(0xffffffffu, amax, o));
    if (lane == 0) p1[wid] = amax;
    __syncthreads();
    float AM = 0.f;
#pragma unroll
    for (int i = 0; i < 8; i++) AM = fmaxf(AM, p1[i]);
    float am = fmaxf(AM, 1e-5f);
    float sa = 127.f / am;

    __nv_bfloat162 q0, q1;
    q0.x = __float2bfloat16(fminf(fmaxf(rintf(v.x * sa), -128.f), 127.f));
    q0.y = __float2bfloat16(fminf(fmaxf(rintf(v.y * sa), -128.f), 127.f));
    q1.x = __float2bfloat16(fminf(fmaxf(rintf(v.z * sa), -128.f), 127.f));
    q1.y = __float2bfloat16(fminf(fmaxf(rintf(v.w * sa), -128.f), 127.f));
    __nv_bfloat162* qp = (__nv_bfloat162*)(g_q + (long)t * HID);
    qp[tid * 2]     = q0;
    qp[tid * 2 + 1] = q1;
    if (tid == 0) g_arecip[t] = am * (1.f / 127.f) * g_ws[1];
}

// ---------------- main GEMM: 128x128 tile, 256 threads, 2 CTA/SM (proven) ----------------
__device__ __forceinline__ void cp16s(uint32_t saddr, const void* g) {
    asm volatile("cp.async.cg.shared.global [%0], [%1], 16;\n" :: "r"(saddr), "l"(g));
}

#define NSTG       3
#define OPER_BYTES 16384
#define STG_BYTES  32768
#define SW(o) ((o) ^ (((o) >> 3) & 0x70))

extern __shared__ __align__(16) char smdyn[];

__global__ void __launch_bounds__(256, 2) bitgemm_kernel(const float* __restrict__ bias,
                                                         float* __restrict__ out) {
    const int tid = threadIdx.x;
    const int lane = tid & 31, warp = tid >> 5;
    const int wm = warp >> 1, wn = warp & 1;
    const long arow0 = (long)blockIdx.y * 128;
    const int brow0 = blockIdx.x * 128;
    const int g = lane >> 2, tg = lane & 3;

    uint32_t sbase;
    asm("{ .reg .u64 t; cvta.to.shared.u64 t, %1; cvt.u32.u64 %0, t; }"
        : "=r"(sbase) : "l"(smdyn));

    const int lr = lane & 7, blk = lane >> 3;
    const int rA = lr + (blk & 1) * 8, cA = (blk >> 1) * 8;
    const int rB = lr + (blk >> 1) * 8, cB = (blk & 1) * 8;

    float acc[2][8][4];
#pragma unroll
    for (int i = 0; i < 2; i++)
#pragma unroll
        for (int j = 0; j < 8; j++)
#pragma unroll
            for (int r = 0; r < 4; r++) acc[i][j][r] = 0.f;

    auto load_chunk = [&](int kt) {
        const uint32_t ab = sbase + (kt % NSTG) * STG_BYTES;
        const uint32_t bb = ab + OPER_BYTES;
        const int k0 = kt * 64;
#pragma unroll
        for (int it = 0; it < 4; it++) {
            int idx = it * 256 + tid;
            int row = idx >> 3, u = idx & 7;
            uint32_t off = row * 128 + u * 16;
            cp16s(ab + SW(off), g_q + (arow0 + row) * HID + k0 + u * 8);
            cp16s(bb + SW(off), g_wq + (long)(brow0 + row) * HID + k0 + u * 8);
        }
        asm volatile("cp.async.commit_group;\n");
    };

    load_chunk(0);
    load_chunk(1);

#pragma unroll 1
    for (int kt = 0; kt < 16; kt++) {
        if (kt < 15) asm volatile("cp.async.wait_group 1;\n");
        else         asm volatile("cp.async.wait_group 0;\n");
        __syncthreads();

        if (kt + 2 < 16) load_chunk(kt + 2);

        const uint32_t ab = sbase + (kt % NSTG) * STG_BYTES;
        const uint32_t bb = ab + OPER_BYTES;
#pragma unroll
        for (int ks = 0; ks < 4; ks++) {
            const int kb = ks * 16;
            unsigned av[2][4];
#pragma unroll
            for (int i = 0; i < 2; i++) {
                uint32_t off = (uint32_t)(wm * 32 + i * 16 + rA) * 128 + (kb + cA) * 2;
                asm volatile("ldmatrix.sync.aligned.m8n8.x4.shared.b16 {%0,%1,%2,%3}, [%4];"
                             : "=r"(av[i][0]), "=r"(av[i][1]), "=r"(av[i][2]), "=r"(av[i][3])
                             : "r"(ab + SW(off)));
            }
#pragma unroll
            for (int jj = 0; jj < 4; jj++) {
                unsigned bv[4];
                uint32_t off = (uint32_t)(wn * 64 + jj * 16 + rB) * 128 + (kb + cB) * 2;
                asm volatile("ldmatrix.sync.aligned.m8n8.x4.shared.b16 {%0,%1,%2,%3}, [%4];"
                             : "=r"(bv[0]), "=r"(bv[1]), "=r"(bv[2]), "=r"(bv[3])
                             : "r"(bb + SW(off)));
#pragma unroll
                for (int jh = 0; jh < 2; jh++) {
                    int j = jj * 2 + jh;
#pragma unroll
                    for (int i = 0; i < 2; i++) {
                        asm volatile(
                            "mma.sync.aligned.m16n8k16.row.col.f32.bf16.bf16.f32 "
                            "{%0,%1,%2,%3}, {%4,%5,%6,%7}, {%8,%9}, {%0,%1,%2,%3};"
                            : "+f"(acc[i][j][0]), "+f"(acc[i][j][1]),
                              "+f"(acc[i][j][2]), "+f"(acc[i][j][3])
                            : "r"(av[i][0]), "r"(av[i][1]), "r"(av[i][2]), "r"(av[i][3]),
                              "r"(bv[jh * 2]), "r"(bv[jh * 2 + 1]));
                    }
                }
            }
        }
    }

    // epilogue: dequant per token + bias (float2 loads & stores)
#pragma unroll
    for (int i = 0; i < 2; i++) {
        long row = arow0 + wm * 32 + i * 16 + g;
        float r0 = g_arecip[row];
        float r1 = g_arecip[row + 8];
#pragma unroll
        for (int j = 0; j < 8; j++) {
            int col = brow0 + wn * 64 + j * 8 + 2 * tg;
            float2 bv = *(const float2*)(bias + col);
            float2 lo = make_float2(acc[i][j][0] * r0 + bv.x, acc[i][j][1] * r0 + bv.y);
            float2 hi = make_float2(acc[i][j][2] * r1 + bv.x, acc[i][j][3] * r1 + bv.y);
            *(float2*)(out + row * ODIM + col)       = lo;
            *(float2*)(out + (row + 8) * ODIM + col) = hi;
        }
    }
}

// ---------------- launch ----------------
extern "C" void kernel_launch(void* const* d_in, const int* in_sizes, int n_in,
                              void* d_out, int out_size) {
    const float* x        = (const float*)d_in[0];
    const float* c        = (const float*)d_in[1];
    const float* w_input  = (const float*)d_in[2];
    const float* w_gate   = (const float*)d_in[3];
    const float* w_down   = (const float*)d_in[4];
    const float* w_output = (const float*)d_in[5];
    const float* b_output = (const float*)d_in[6];
    const float* w_norm   = (const float*)d_in[7];
    const float* w_outp   = (const float*)d_in[8];
    const float* b_outp   = (const float*)d_in[9];
    const float* w_bit    = (const float*)d_in[10];
    const float* b_bit    = (const float*)d_in[11];
    const float* w_bn     = (const float*)d_in[12];
    float* out = (float*)d_out;

    float *p_h, *p_u, *p_z, *p_o, *p_mod;
    cudaGetSymbolAddress((void**)&p_h,   g_h);
    cudaGetSymbolAddress((void**)&p_u,   g_u);
    cudaGetSymbolAddress((void**)&p_z,   g_z);
    cudaGetSymbolAddress((void**)&p_o,   g_o);
    cudaGetSymbolAddress((void**)&p_mod, g_mod);

    // weight quant path
    wabs_partial_kernel<<<1024, 256>>>(w_bit);
    wquant_kernel<<<(ODIM * HID / 4) / 256, 256>>>(w_bit);

    // modulation chain (B=4)
    gemm4_silu_kernel<<<512, 256>>>(c, w_input, p_h, HID, HID);
    gemm4gate_kernel<<<704, 256>>>(p_h, w_gate, p_u);          // 2*INTERD/8 = 704
    gemm4_kernel<<<512, 256>>>(p_u, w_down, nullptr, p_z, INTERD, HID);
    gemm4_kernel<<<1024, 256>>>(p_z, w_output, b_output, p_o, HID, 2 * HID);
    gemm4_rms_kernel<<<512, 256>>>(w_outp, b_outp, w_norm, p_mod);  // 4*2048/2/8 = 512

    // per-token normalize + bf16-int quantize
    aq_kernel<<<NTOK, 256>>>(x, w_bn);

    // main GEMM
    static const int smem_bytes = NSTG * STG_BYTES;   // 98304
    cudaFuncSetAttribute(bitgemm_kernel, cudaFuncAttributeMaxDynamicSharedMemorySize, smem_bytes);
    dim3 ggrid(8, 256);
    bitgemm_kernel<<<ggrid, 256, smem_bytes>>>(b_bit, out);
}